// round 13
// baseline (speedup 1.0000x reference)
#include <cuda_runtime.h>
#include <cuda_bf16.h>
#include <cstdint>
#include <math.h>

#define BB 2
#define CC 256
#define NPix 3600
#define NCls 2
#define HOUT 473
#define WOUT 473
typedef __nv_bfloat16 bf16;
typedef __nv_bfloat162 bf162;

static const size_t CN = (size_t)CC*NPix, NN = (size_t)NPix*NPix, NCn = (size_t)NPix*CC;

__device__ bf16 g_Vab[BB*CC*NPix], g_Vbb[BB*CC*NPix];
__device__ bf16 g_Web[CC*CC];
__device__ bf16 g_wr1[9*CC*768], g_wr2[9*CC*512];
__device__ bf16 g_VaT[BB*NPix*CC], g_VbT[BB*NPix*CC], g_DaT[BB*NPix*CC], g_WvT[BB*NPix*CC];
__device__ bf16 g_E[(size_t)BB*NPix*NPix], g_ET[(size_t)BB*NPix*NPix];
__device__ bf16 g_a1Tb[BB*NPix*CC], g_a2Tb[BB*NPix*CC];
__device__ float g_x1T[BB*NPix*CC], g_x2T[BB*NPix*CC];
__device__ float g_bp[2*58*CC], g_bq[2*58*CC];
__device__ float g_bnsc[2*CC], g_bnsh[2*CC];
__device__ float g_y1[BB*NCls*NPix], g_y2[BB*NCls*NPix];

__device__ __forceinline__ uint32_t smem_u32(const void* p){
    uint32_t a; asm("{ .reg .u64 t; cvta.to.shared.u64 t, %1; cvt.u32.u64 %0, t; }":"=r"(a):"l"(p)); return a;
}
__device__ __forceinline__ void cpa16(uint32_t d, const void* s, bool v){
    asm volatile("cp.async.cg.shared.global [%0],[%1],16,%2;"::"r"(d),"l"(s),"r"(v?16:0));
}
__device__ __forceinline__ void ldmx4(uint32_t* r, uint32_t a){
    asm volatile("ldmatrix.sync.aligned.m8n8.x4.shared.b16 {%0,%1,%2,%3},[%4];"
        :"=r"(r[0]),"=r"(r[1]),"=r"(r[2]),"=r"(r[3]):"r"(a));
}
__device__ __forceinline__ void mma_bf16(float* c, const uint32_t* a, const uint32_t* b){
    asm volatile("mma.sync.aligned.m16n8k16.row.col.f32.bf16.bf16.f32 "
        "{%0,%1,%2,%3},{%4,%5,%6,%7},{%8,%9},{%0,%1,%2,%3};"
        :"+f"(c[0]),"+f"(c[1]),"+f"(c[2]),"+f"(c[3])
        :"r"(a[0]),"r"(a[1]),"r"(a[2]),"r"(a[3]),"r"(b[0]),"r"(b[1]));
}

// ===== k64 path: 128x128 tile, 3 stages, pitch 144B =====
#define STG64 36864
#define GS64  (3*STG64)

#define MMA_COMPUTE64(ta, tb) \
    _Pragma("unroll") \
    for (int s = 0; s < 4; s++) { \
        uint32_t af[4][4], bq[4][2]; \
        _Pragma("unroll") \
        for (int mt = 0; mt < 4; mt++) \
            ldmx4(af[mt], (ta) + (uint32_t)((wm*64+mt*16+(g&1)*8+r8)*144 + (g>>1)*16 + s*32)); \
        _Pragma("unroll") \
        for (int np = 0; np < 2; np++) { \
            uint32_t t4[4]; \
            ldmx4(t4, (tb) + (uint32_t)((wn*32+np*16+(g>>1)*8+r8)*144 + (g&1)*16 + s*32)); \
            bq[np*2][0]=t4[0]; bq[np*2][1]=t4[1]; bq[np*2+1][0]=t4[2]; bq[np*2+1][1]=t4[3]; \
        } \
        _Pragma("unroll") \
        for (int mt = 0; mt < 4; mt++) \
            _Pragma("unroll") \
            for (int nt = 0; nt < 4; nt++) \
                mma_bf16(acc[mt][nt], af[mt], bq[nt]); \
    }

#define GEMM_MAINLOOP64(Aptr, Bptr, MMd, NNd, KKd, llda, lldb) \
    const int rowL = tid>>1, hb = (tid&1)*32; \
    const bool vA = (m0+rowL)<(MMd), vB = (n0+rowL)<(NNd); \
    const bf16* pA = (Aptr) + (vA?((size_t)(m0+rowL)*(llda)):0) + hb; \
    const bf16* pB = (Bptr) + (vB?((size_t)(n0+rowL)*(lldb)):0) + hb; \
    const uint32_t dA = rowL*144+hb*2, dB = 18432+rowL*144+hb*2; \
    auto LD = [&](int c){ \
        if (c < NC) { \
            uint32_t st = sb + (c%3)*STG64; \
            int k0 = c<<6; \
            _Pragma("unroll") \
            for (int q=0;q<4;q++){ \
                bool ok = (k0+hb+q*8)<(KKd); \
                cpa16(st+dA+q*16, pA+k0+q*8, vA&&ok); \
                cpa16(st+dB+q*16, pB+k0+q*8, vB&&ok); \
            } \
        } \
        asm volatile("cp.async.commit_group;":::"memory"); \
    }; \
    LD(0); LD(1); \
    for (int c=0;c<NC;c++){ \
        asm volatile("cp.async.wait_group 1;":::"memory"); \
        __syncthreads(); \
        uint32_t ta = sb+(c%3)*STG64, tb = ta+18432; \
        MMA_COMPUTE64(ta, tb); \
        LD(c+2); \
    }

// generic k64 GEMM: C[M,N]=A[M,K]*B^T, A=[i][k], B=[j][k]. OUTM: 0=f32, 1=bf16
template<int OUTM>
__global__ void __launch_bounds__(256,2)
bgemm(const bf16* __restrict__ A, const bf16* __restrict__ B, void* __restrict__ Cv,
      int Md, int Nd, int Kd, int lda, int ldb, int ldc, size_t sA, size_t sB, size_t sC)
{
    extern __shared__ char smc[];
    const int z = blockIdx.z;
    const bf16* Ap = A+(size_t)z*sA;
    const bf16* Bp = B+(size_t)z*sB;
    const int m0 = blockIdx.y*128, n0 = blockIdx.x*128;
    const int tid = threadIdx.x, lane = tid&31, wid = tid>>5;
    const int wm = wid>>2, wn = wid&3, g = lane>>3, r8 = lane&7;
    uint32_t sb = smem_u32(smc);
    float acc[4][4][4];
#pragma unroll
    for (int a=0;a<4;a++)
#pragma unroll
        for (int b=0;b<4;b++)
#pragma unroll
            for (int c=0;c<4;c++) acc[a][b][c]=0.f;
    const int NC = (Kd+63)>>6;
    GEMM_MAINLOOP64(Ap, Bp, Md, Nd, Kd, lda, ldb)
#pragma unroll
    for (int mt=0;mt<4;mt++){
        int r0 = m0+wm*64+mt*16+(lane>>2);
#pragma unroll
        for (int nt=0;nt<4;nt++){
            int c0 = n0+wn*32+nt*8+(lane&3)*2;
            if (c0 >= Nd) continue;
            if (OUTM==0){
                float* C=(float*)Cv+(size_t)z*sC;
                if (r0<Md)   *(float2*)&C[(size_t)r0*ldc+c0]     = make_float2(acc[mt][nt][0],acc[mt][nt][1]);
                if (r0+8<Md) *(float2*)&C[(size_t)(r0+8)*ldc+c0] = make_float2(acc[mt][nt][2],acc[mt][nt][3]);
            } else {
                bf16* C=(bf16*)Cv+(size_t)z*sC;
                if (r0<Md)   *(bf162*)&C[(size_t)r0*ldc+c0]     = __floats2bfloat162_rn(acc[mt][nt][0],acc[mt][nt][1]);
                if (r0+8<Md) *(bf162*)&C[(size_t)(r0+8)*ldc+c0] = __floats2bfloat162_rn(acc[mt][nt][2],acc[mt][nt][3]);
            }
        }
    }
}

// S GEMM (k64): E=exp(WvT·VbT^T) and ET via swizzled smem
__global__ void __launch_bounds__(256,2)
sgemm(const bf16* __restrict__ WvT, const bf16* __restrict__ VbT,
      bf16* __restrict__ Ep, bf16* __restrict__ ETp)
{
    extern __shared__ char smc[];
    const int z = blockIdx.z;
    const bf16* A = WvT + (size_t)z*NCn;
    const bf16* B = VbT + (size_t)z*NCn;
    bf16* Eb  = Ep  + (size_t)z*NN;
    bf16* ETb = ETp + (size_t)z*NN;
    const int m0 = blockIdx.y*128, n0 = blockIdx.x*128;
    const int tid = threadIdx.x, lane = tid&31, wid = tid>>5;
    const int wm = wid>>2, wn = wid&3, g = lane>>3, r8 = lane&7;
    uint32_t sb = smem_u32(smc);
    float acc[4][4][4];
#pragma unroll
    for (int a=0;a<4;a++)
#pragma unroll
        for (int b=0;b<4;b++)
#pragma unroll
            for (int c=0;c<4;c++) acc[a][b][c]=0.f;
    const int NC = 4;   // K=256
    GEMM_MAINLOOP64(A, B, NPix, NPix, CC, CC, CC)

    __syncthreads();
    bf16* sh = (bf16*)smc;
#pragma unroll
    for (int mt=0;mt<4;mt++){
        int rl0 = wm*64+mt*16+(lane>>2);
        int r0 = m0+rl0;
        bool rok0 = r0<NPix, rok1 = (r0+8)<NPix;
#pragma unroll
        for (int nt=0;nt<4;nt++){
            int cl0 = wn*32+nt*8+(lane&3)*2;
            int c0 = n0+cl0;
            bool cok = c0<NPix;
            float x0=__expf(acc[mt][nt][0]),x1=__expf(acc[mt][nt][1]);
            float x2=__expf(acc[mt][nt][2]),x3=__expf(acc[mt][nt][3]);
            if (cok) {
                if (rok0) *(bf162*)&Eb[(size_t)r0*NPix+c0]     = __floats2bfloat162_rn(x0,x1);
                if (rok1) *(bf162*)&Eb[(size_t)(r0+8)*NPix+c0] = __floats2bfloat162_rn(x2,x3);
            }
#define TST(rr,cc,xx) sh[(cc)*136 + (((((rr)>>3)^((cc)>>3))&15)<<3) + ((rr)&7)] = __float2bfloat16(xx)
            TST(rl0,   cl0,   x0); TST(rl0,   cl0+1, x1);
            TST(rl0+8, cl0,   x2); TST(rl0+8, cl0+1, x3);
#undef TST
        }
    }
    __syncthreads();
#pragma unroll
    for (int rr=0; rr<16; rr++){
        int cp2 = wid*16 + rr;
        int mg = n0 + cp2;
        if (mg >= NPix) continue;
        int cb = cp2>>3;
        int rb = lane>>1, half = lane&1;
        int ng = m0 + rb*8 + half*4;
        if (ng >= NPix) continue;
        uint2 v = *(uint2*)(sh + cp2*136 + (((rb^cb)&15)<<3) + half*4);
        *(uint2*)&ETb[(size_t)mg*NPix + ng] = v;
    }
}

// ===== zfused (k32 path, unchanged from R12) =====
#define ZSTG 25600
#define ZSMEM (4*ZSTG)
__global__ void __launch_bounds__(256,2)
zfused(const bf16* __restrict__ E, const bf16* __restrict__ ET,
       const bf16* __restrict__ Vab, const bf16* __restrict__ Vbb,
       const float* __restrict__ gw,
       bf16* __restrict__ a1b, bf16* __restrict__ a2b)
{
    extern __shared__ char smc[];
    int z = blockIdx.z, br = z>>1, b = z&1;
    const bf16* A = (br?ET:E) + (size_t)b*NN;
    const bf16* B = (br?Vab:Vbb) + (size_t)b*CN;
    bf16* out = (br?a2b:a1b) + (size_t)b*NCn;
    const int m0 = blockIdx.y*64;
    const int tid = threadIdx.x, lane = tid&31, wid = tid>>5;
    const int wm = wid>>2, wn = wid&3, g = lane>>3, r8 = lane&7;
    uint32_t sb = smem_u32(smc);
    float acc[2][8][4];
#pragma unroll
    for (int a=0;a<2;a++)
#pragma unroll
        for (int bb=0;bb<8;bb++)
#pragma unroll
            for (int c=0;c<4;c++) acc[a][bb][c]=0.f;
    const int NC = 113;

    const int rowA = tid>>2, sgA = tid&3;
    const bool vA = (m0+rowA)<NPix;
    const bf16* pA = A + (vA?((size_t)(m0+rowA)*NPix):0) + sgA*8;
    const bf16* pB = B + (size_t)rowA*NPix + sgA*8;
    const uint32_t dA = rowA*80 + sgA*16;
    const uint32_t dB = 5120 + rowA*80 + sgA*16;
    auto LD = [&](int c){
        if (c < NC) {
            uint32_t st = sb + (c&3)*ZSTG;
            int k0 = c<<5;
            bool kok = (k0+sgA*8) < NPix;
            cpa16(st+dA, pA+k0, vA&&kok);
#pragma unroll
            for (int q=0;q<4;q++)
                cpa16(st+dB + q*64*80, pB + (size_t)q*64*NPix + k0, kok);
        }
        asm volatile("cp.async.commit_group;":::"memory");
    };
    LD(0); LD(1); LD(2);
    float rs = 0.f;
    for (int c=0;c<NC;c++){
        asm volatile("cp.async.wait_group 2;":::"memory");
        __syncthreads();
        uint32_t ta = sb+(c&3)*ZSTG, tb = ta+5120;
        {
            const uint4 v4 = *(const uint4*)(smc + (size_t)(c&3)*ZSTG + rowA*80 + sgA*16);
            const uint32_t vv[4] = {v4.x, v4.y, v4.z, v4.w};
#pragma unroll
            for (int u=0;u<4;u++){
                float2 f = __bfloat1622float2(*(const bf162*)&vv[u]);
                rs += f.x + f.y;
            }
        }
#pragma unroll
        for (int s=0;s<2;s++){
            uint32_t af[2][4], bq[8][2];
#pragma unroll
            for (int mt=0;mt<2;mt++)
                ldmx4(af[mt], ta + (uint32_t)((wm*32+mt*16+(g&1)*8+r8)*80 + (g>>1)*16 + s*32));
#pragma unroll
            for (int np=0;np<4;np++){
                uint32_t t4[4];
                ldmx4(t4, tb + (uint32_t)((wn*64+np*16+(g>>1)*8+r8)*80 + (g&1)*16 + s*32));
                bq[np*2][0]=t4[0]; bq[np*2][1]=t4[1]; bq[np*2+1][0]=t4[2]; bq[np*2+1][1]=t4[3];
            }
#pragma unroll
            for (int mt=0;mt<2;mt++)
#pragma unroll
                for (int nt=0;nt<8;nt++)
                    mma_bf16(acc[mt][nt], af[mt], bq[nt]);
        }
        LD(c+3);
    }
    rs += __shfl_xor_sync(~0u, rs, 1);
    rs += __shfl_xor_sync(~0u, rs, 2);

    float gwv[8][2];
#pragma unroll
    for (int nt=0;nt<8;nt++){
        int c0 = wn*64+nt*8+(lane&3)*2;
        gwv[nt][0]=gw[c0]; gwv[nt][1]=gw[c0+1];
    }
    float praw[2][2]={{0,0},{0,0}};
#pragma unroll
    for (int mt=0;mt<2;mt++)
#pragma unroll
        for (int nt=0;nt<8;nt++){
            praw[mt][0] += gwv[nt][0]*acc[mt][nt][0] + gwv[nt][1]*acc[mt][nt][1];
            praw[mt][1] += gwv[nt][0]*acc[mt][nt][2] + gwv[nt][1]*acc[mt][nt][3];
        }
#pragma unroll
    for (int mt=0;mt<2;mt++)
#pragma unroll
        for (int o=1;o<=2;o<<=1){
            praw[mt][0]+=__shfl_xor_sync(~0u,praw[mt][0],o);
            praw[mt][1]+=__shfl_xor_sync(~0u,praw[mt][1],o);
        }
    __syncthreads();
    float* dotv  = (float*)smc;
    float* rsums = (float*)smc + 256;
    if ((lane&3)==0){
#pragma unroll
        for (int mt=0;mt<2;mt++){
            int rl = wm*32+mt*16+(lane>>2);
            dotv[wn*64 + rl]     = praw[mt][0];
            dotv[wn*64 + rl + 8] = praw[mt][1];
        }
    }
    if (sgA==0) rsums[rowA] = rs;
    __syncthreads();
#pragma unroll
    for (int mt=0;mt<2;mt++){
#pragma unroll
        for (int hf=0;hf<2;hf++){
            int rl = wm*32+mt*16+hf*8+(lane>>2);
            int r = m0+rl;
            if (r >= NPix) continue;
            float d = dotv[rl] + dotv[64+rl] + dotv[128+rl] + dotv[192+rl];
            float v = 1.f/rsums[rl];
            float mul = v/(1.f+__expf(-d*v));
#pragma unroll
            for (int nt=0;nt<8;nt++){
                int c0 = wn*64+nt*8+(lane&3)*2;
                *(bf162*)&out[(size_t)r*CC+c0] =
                    __floats2bfloat162_rn(acc[mt][nt][hf*2]*mul, acc[mt][nt][hf*2+1]*mul);
            }
        }
    }
}

// convs (k64): z=0,1 conv1 (3 srcs), z=2,3 conv2 (2 srcs); 9 shifted accumulated GEMMs
__global__ void __launch_bounds__(256,2)
convpair(const bf16* __restrict__ a1b, const bf16* __restrict__ a2b,
         const bf16* __restrict__ VaT, const bf16* __restrict__ VbT, const bf16* __restrict__ DaT,
         const bf16* __restrict__ wr1, const bf16* __restrict__ wr2,
         float* __restrict__ x1T, float* __restrict__ x2T)
{
    extern __shared__ char smc[];
    int zz = blockIdx.z, br = zz>>1, b = zz&1;
    const bf16 *s0 = br?a2b:a1b, *s1 = br?VbT:VaT, *s2 = br?VbT:DaT;
    const bf16 *W = br?wr2:wr1;
    float* out = br?x2T:x1T;
    const int SR = br?2:3;
    const int LDB = SR*256, KPC = SR*4, NC = 9*KPC;   // k64 chunks
    const size_t so = (size_t)b*NCn;
    const int m0 = blockIdx.y*128, n0 = blockIdx.x*128;
    const int tid = threadIdx.x, lane = tid&31, wid = tid>>5;
    const int wm = wid>>2, wn = wid&3, g = lane>>3, r8 = lane&7;
    uint32_t sb = smem_u32(smc);
    float acc[4][4][4];
#pragma unroll
    for (int a=0;a<4;a++)
#pragma unroll
        for (int bb=0;bb<4;bb++)
#pragma unroll
            for (int c=0;c<4;c++) acc[a][bb][c]=0.f;

    const int rowL = tid>>1, hb = (tid&1)*32;
    const int j = m0+rowL;
    const bool jv = j<NPix;
    const int h = (jv?j:0)/60, w = (jv?j:0) - ((jv?j:0)/60)*60;
    uint32_t vmask = 0;
#pragma unroll
    for (int rr=0;rr<9;rr++){
        int dh = rr/3-1, dw = rr-(rr/3)*3-1;
        if (jv && (unsigned)(h+dh)<60u && (unsigned)(w+dw)<60u) vmask |= 1u<<rr;
    }
    const size_t jb = (size_t)(jv?j:0)*CC + hb;
    const bf16 *pS0 = s0+so+jb, *pS1 = s1+so+jb, *pS2 = s2+so+jb;
    const bf16 *pW = W + (size_t)(n0+rowL)*LDB + hb;
    const uint32_t dAs = rowL*144+hb*2, dBs = 18432+rowL*144+hb*2;

    int ld_vc = 0, ld_rr = 0, ld_kc = 0, ld_dh = -1, ld_dw = -1;
    size_t woff = 0;
    auto LD = [&](){
        if (ld_vc < NC) {
            uint32_t st = sb + (ld_vc%3)*STG64;
            bool vv = (vmask>>ld_rr)&1;
            int off = ld_dh*60 + ld_dw;
            int srcSel = ld_kc>>2;
            const bf16* sp = (srcSel==0)?pS0:((srcSel==1)?pS1:pS2);
            const bf16* ap = sp + (intptr_t)off*CC + (ld_kc&3)*64;
#pragma unroll
            for (int q=0;q<4;q++){
                cpa16(st+dAs+q*16, vv?(ap+q*8):s0, vv);
                cpa16(st+dBs+q*16, pW+woff+q*8, true);
            }
            ld_vc++; ld_kc++; woff += 64;
            if (ld_kc == KPC) {
                ld_kc = 0; ld_rr++;
                woff += (size_t)(CC-1)*LDB;
                ld_dw++; if (ld_dw==2){ ld_dw=-1; ld_dh++; }
            }
        }
        asm volatile("cp.async.commit_group;":::"memory");
    };
    LD(); LD();
    for (int c=0;c<NC;c++){
        asm volatile("cp.async.wait_group 1;":::"memory");
        __syncthreads();
        uint32_t ta = sb+(c%3)*STG64, tb = ta+18432;
        MMA_COMPUTE64(ta, tb);
        LD();
    }
    float* C = out + so;
#pragma unroll
    for (int mt=0;mt<4;mt++){
        int r0 = m0+wm*64+mt*16+(lane>>2);
#pragma unroll
        for (int nt=0;nt<4;nt++){
            int c0 = n0+wn*32+nt*8+(lane&3)*2;
            if (r0<NPix)   *(float2*)&C[(size_t)r0*CC+c0]     = make_float2(acc[mt][nt][0],acc[mt][nt][1]);
            if (r0+8<NPix) *(float2*)&C[(size_t)(r0+8)*CC+c0] = make_float2(acc[mt][nt][2],acc[mt][nt][3]);
        }
    }
}

__global__ void wprep(const float* __restrict__ W_e, const float* __restrict__ c1w,
                      const float* __restrict__ c2w, bf16* __restrict__ Web,
                      bf16* __restrict__ wr1, bf16* __restrict__ wr2)
{
    int idx = blockIdx.x*256+threadIdx.x;
    const int N0 = CC*CC, N1 = 9*CC*768, N2 = 9*CC*512;
    if (idx < N0) { Web[idx] = __float2bfloat16(W_e[idx]); return; }
    idx -= N0;
    if (idx < N1) {
        int r = idx/(CC*768), rem = idx - r*(CC*768);
        int co = rem/768, ci = rem - co*768;
        wr1[idx] = __float2bfloat16(c1w[(size_t)co*768*9 + ci*9 + r]);
        return;
    }
    idx -= N1;
    if (idx < N2) {
        int r = idx/(CC*512), rem = idx - r*(CC*512);
        int co = rem/512, ci = rem - co*512;
        wr2[idx] = __float2bfloat16(c2w[(size_t)co*512*9 + ci*9 + r]);
    }
}

__global__ void trans3(const float* __restrict__ Va, const float* __restrict__ Vb,
                       const float* __restrict__ Da,
                       bf16* __restrict__ VaT, bf16* __restrict__ VbT, bf16* __restrict__ DaT,
                       bf16* __restrict__ Vab, bf16* __restrict__ Vbb)
{
    __shared__ float t[32][33];
    int z = blockIdx.z, src = z>>1, b = z&1;
    const float* in = (src==0?Va:(src==1?Vb:Da)) + (size_t)b*CN;
    bf16* outT = (src==0?VaT:(src==1?VbT:DaT)) + (size_t)b*NCn;
    bf16* outN = (src==0?Vab:(src==1?Vbb:(bf16*)nullptr));
    if (outN) outN += (size_t)b*CN;
    int c0 = blockIdx.x*32, r0 = blockIdx.y*32;
    int tx = threadIdx.x&31, ty = threadIdx.x>>5;
#pragma unroll
    for (int i=0;i<4;i++){
        int rr=r0+ty+i*8, cc=c0+tx;
        if (cc<NPix){
            float v = in[(size_t)rr*NPix+cc];
            t[ty+i*8][tx] = v;
            if (outN) outN[(size_t)rr*NPix+cc] = __float2bfloat16(v);
        }
    }
    __syncthreads();
#pragma unroll
    for (int i=0;i<4;i++){
        int cc=c0+ty+i*8, rr=r0+tx;
        if (cc<NPix) outT[(size_t)cc*CC+rr] = __float2bfloat16(t[tx][ty+i*8]);
    }
}

__global__ void bnpart_k(const float* __restrict__ x1T, const float* __restrict__ x2T,
                         float* __restrict__ ps, float* __restrict__ pq)
{
    int z = blockIdx.z;
    const float* x = z?x2T:x1T;
    int c = threadIdx.x, b = blockIdx.y, blk = blockIdx.x;
    int n0 = blk*128, nend = min(n0+128, NPix);
    const float* xp = x + (size_t)b*NCn + c;
    float s=0.f, q=0.f;
    for (int n=n0;n<nend;n++){ float v=xp[(size_t)n*CC]; s+=v; q+=v*v; }
    int p = z*58 + b*29 + blk;
    ps[p*CC+c]=s; pq[p*CC+c]=q;
}

__global__ void bncomb_k(const float* __restrict__ ps, const float* __restrict__ pq,
                         const float* __restrict__ g1, const float* __restrict__ b1,
                         const float* __restrict__ g2, const float* __restrict__ b2,
                         float* __restrict__ sc, float* __restrict__ sh)
{
    int c = threadIdx.x, z = blockIdx.x;
    float s=0.f, q=0.f;
    for (int p=z*58;p<z*58+58;p++){ s+=ps[p*CC+c]; q+=pq[p*CC+c]; }
    const float inv = 1.f/(BB*NPix);
    float mean=s*inv, var=q*inv-mean*mean;
    float k = (z?g2:g1)[c]*rsqrtf(var+1e-5f);
    sc[z*CC+c]=k; sh[z*CC+c]=(z?b2:b1)[c]-mean*k;
}

__global__ void bncls_k(const float* __restrict__ x1T, const float* __restrict__ x2T,
                        const float* __restrict__ sc, const float* __restrict__ sh,
                        const float* __restrict__ c1w, const float* __restrict__ c1b,
                        const float* __restrict__ c2w, const float* __restrict__ c2b,
                        float* __restrict__ y1, float* __restrict__ y2)
{
    int z = blockIdx.z;
    const float* x = z?x2T:x1T;
    const float* cw = z?c2w:c1w;
    const float* cb = z?c2b:c1b;
    float* y = z?y2:y1;
    __shared__ float ssc[CC], ssh[CC], w0[CC], w1[CC];
    int tid = threadIdx.x;
    for (int c=tid;c<CC;c+=256){ ssc[c]=sc[z*CC+c]; ssh[c]=sh[z*CC+c]; w0[c]=cw[c]; w1[c]=cw[CC+c]; }
    __syncthreads();
    int lane=tid&31, wid=tid>>5;
    int p = blockIdx.x*8+wid, b = blockIdx.y;
    const float* xp = x + ((size_t)b*NPix+p)*CC + lane*8;
    float4 u0=*(const float4*)xp, u1=*(const float4*)(xp+4);
    float vv[8]={u0.x,u0.y,u0.z,u0.w,u1.x,u1.y,u1.z,u1.w};
    int c8=lane*8;
    float a0=0.f, a1=0.f;
#pragma unroll
    for (int u=0;u<8;u++){
        float v = fmaxf(vv[u]*ssc[c8+u]+ssh[c8+u], 0.f);
        a0 += v*w0[c8+u]; a1 += v*w1[c8+u];
    }
#pragma unroll
    for (int o=16;o;o>>=1){ a0+=__shfl_xor_sync(~0u,a0,o); a1+=__shfl_xor_sync(~0u,a1,o); }
    if (lane==0){
        y[(size_t)(b*NCls+0)*NPix+p] = a0+cb[0];
        y[(size_t)(b*NCls+1)*NPix+p] = a1+cb[1];
    }
}

__global__ void resize_k(float* __restrict__ out)
{
    const size_t per = (size_t)BB*NCls*HOUT*WOUT;
    size_t idx = (size_t)blockIdx.x*256+threadIdx.x;
    if (idx >= 2*per) return;
    int t = idx >= per;
    size_t r = idx - (size_t)t*per;
    int x=(int)(r%WOUT); r/=WOUT;
    int y=(int)(r%HOUT); r/=HOUT;
    int kc=(int)(r%NCls); int b=(int)(r/NCls);
    const float* src = (t?g_y2:g_y1) + (size_t)(b*NCls+kc)*NPix;
    const float sc = 60.f/473.f;
    float syf=(y+0.5f)*sc-0.5f, sxf=(x+0.5f)*sc-0.5f;
    float fy0=floorf(syf), fx0=floorf(sxf);
    float fy=syf-fy0, fx=sxf-fx0;
    int y0=max((int)fy0,0), x0=max((int)fx0,0);
    int y1i=min((int)fy0+1,59), x1i=min((int)fx0+1,59);
    float v00=src[y0*60+x0], v01=src[y0*60+x1i], v10=src[y1i*60+x0], v11=src[y1i*60+x1i];
    float vt=v00+(v01-v00)*fx, vb=v10+(v11-v10)*fx;
    out[idx] = 1.f/(1.f+__expf(-(vt+(vb-vt)*fy)));
}

extern "C" void kernel_launch(void* const* d_in, const int* in_sizes, int n_in,
                              void* d_out, int out_size)
{
    const float *V_a=(const float*)d_in[0], *V_b=(const float*)d_in[1], *D_a=(const float*)d_in[2];
    const float *W_e=(const float*)d_in[3], *gate_w=(const float*)d_in[4];
    const float *c1w=(const float*)d_in[5], *c2w=(const float*)d_in[6];
    const float *bn1g=(const float*)d_in[7], *bn1b=(const float*)d_in[8];
    const float *bn2g=(const float*)d_in[9], *bn2b=(const float*)d_in[10];
    const float *cl1w=(const float*)d_in[11], *cl1b=(const float*)d_in[12];
    const float *cl2w=(const float*)d_in[13], *cl2b=(const float*)d_in[14];
    float* out = (float*)d_out;

    bf16 *Vab,*Vbb,*Web,*wr1,*wr2,*VaT,*VbT,*DaT,*WvT,*E,*ET,*a1b,*a2b;
    float *x1T,*x2T,*bp,*bq,*bsc,*bsh,*y1,*y2;
    cudaGetSymbolAddress((void**)&Vab,g_Vab);  cudaGetSymbolAddress((void**)&Vbb,g_Vbb);
    cudaGetSymbolAddress((void**)&Web,g_Web);  cudaGetSymbolAddress((void**)&wr1,g_wr1);
    cudaGetSymbolAddress((void**)&wr2,g_wr2);  cudaGetSymbolAddress((void**)&VaT,g_VaT);
    cudaGetSymbolAddress((void**)&VbT,g_VbT);  cudaGetSymbolAddress((void**)&DaT,g_DaT);
    cudaGetSymbolAddress((void**)&WvT,g_WvT);  cudaGetSymbolAddress((void**)&E,g_E);
    cudaGetSymbolAddress((void**)&ET,g_ET);
    cudaGetSymbolAddress((void**)&a1b,g_a1Tb); cudaGetSymbolAddress((void**)&a2b,g_a2Tb);
    cudaGetSymbolAddress((void**)&x1T,g_x1T);  cudaGetSymbolAddress((void**)&x2T,g_x2T);
    cudaGetSymbolAddress((void**)&bp,g_bp);    cudaGetSymbolAddress((void**)&bq,g_bq);
    cudaGetSymbolAddress((void**)&bsc,g_bnsc); cudaGetSymbolAddress((void**)&bsh,g_bnsh);
    cudaGetSymbolAddress((void**)&y1,g_y1);    cudaGetSymbolAddress((void**)&y2,g_y2);

    cudaFuncSetAttribute(bgemm<1>, cudaFuncAttributeMaxDynamicSharedMemorySize, GS64);
    cudaFuncSetAttribute(sgemm,    cudaFuncAttributeMaxDynamicSharedMemorySize, GS64);
    cudaFuncSetAttribute(zfused,   cudaFuncAttributeMaxDynamicSharedMemorySize, ZSMEM);
    cudaFuncSetAttribute(convpair, cudaFuncAttributeMaxDynamicSharedMemorySize, GS64);

    const int WTOT = CC*CC + 9*CC*768 + 9*CC*512;
    wprep<<<(WTOT+255)/256,256>>>(W_e, c1w, c2w, Web, wr1, wr2);
    trans3<<<dim3(113,8,6),256>>>(V_a, V_b, D_a, VaT, VbT, DaT, Vab, Vbb);
    bgemm<1><<<dim3(2,29,BB),256,GS64>>>(VaT, Web, WvT, NPix, CC, CC, CC, CC, CC, NCn, 0, NCn);
    sgemm<<<dim3(29,29,BB),256,GS64>>>(WvT, VbT, E, ET);
    zfused<<<dim3(1,57,4),256,ZSMEM>>>(E, ET, Vab, Vbb, gate_w, a1b, a2b);
    convpair<<<dim3(2,29,4),256,GS64>>>(a1b, a2b, VaT, VbT, DaT, wr1, wr2, x1T, x2T);
    bnpart_k<<<dim3(29,BB,2),256>>>(x1T, x2T, bp, bq);
    bncomb_k<<<2,256>>>(bp, bq, bn1g, bn1b, bn2g, bn2b, bsc, bsh);
    bncls_k<<<dim3(450,BB,2),256>>>(x1T, x2T, bsc, bsh, cl1w, cl1b, cl2w, cl2b, y1, y2);
    const size_t total = 2ull*BB*NCls*HOUT*WOUT;
    resize_k<<<(int)((total+255)/256),256>>>(out);
}

// round 16
// speedup vs baseline: 1.0652x; 1.0652x over previous
#include <cuda_runtime.h>
#include <cuda_bf16.h>
#include <cstdint>
#include <math.h>

#define BB 2
#define CC 256
#define NPix 3600
#define NCls 2
#define HOUT 473
#define WOUT 473
typedef __nv_bfloat16 bf16;
typedef __nv_bfloat162 bf162;

static const size_t CN = (size_t)CC*NPix, NN = (size_t)NPix*NPix, NCn = (size_t)NPix*CC;

__device__ bf16 g_Vab[BB*CC*NPix], g_Vbb[BB*CC*NPix];
__device__ bf16 g_Web[CC*CC];
__device__ bf16 g_wr1[9*CC*768], g_wr2[9*CC*512];
__device__ bf16 g_VaT[BB*NPix*CC], g_VbT[BB*NPix*CC], g_DaT[BB*NPix*CC], g_WvT[BB*NPix*CC];
__device__ bf16 g_E[(size_t)BB*NPix*NPix], g_ET[(size_t)BB*NPix*NPix];
__device__ bf16 g_a1Tb[BB*NPix*CC], g_a2Tb[BB*NPix*CC];
__device__ float g_x1T[BB*NPix*CC], g_x2T[BB*NPix*CC];
__device__ float g_bp[2*58*CC], g_bq[2*58*CC];
__device__ float g_bnsc[2*CC], g_bnsh[2*CC];
__device__ float g_y1[BB*NCls*NPix], g_y2[BB*NCls*NPix];

__device__ __forceinline__ uint32_t smem_u32(const void* p){
    uint32_t a; asm("{ .reg .u64 t; cvta.to.shared.u64 t, %1; cvt.u32.u64 %0, t; }":"=r"(a):"l"(p)); return a;
}
__device__ __forceinline__ void cpa16(uint32_t d, const void* s, bool v){
    asm volatile("cp.async.cg.shared.global [%0],[%1],16,%2;"::"r"(d),"l"(s),"r"(v?16:0));
}
__device__ __forceinline__ void ldmx4(uint32_t* r, uint32_t a){
    asm volatile("ldmatrix.sync.aligned.m8n8.x4.shared.b16 {%0,%1,%2,%3},[%4];"
        :"=r"(r[0]),"=r"(r[1]),"=r"(r[2]),"=r"(r[3]):"r"(a));
}
__device__ __forceinline__ void mma_bf16(float* c, const uint32_t* a, const uint32_t* b){
    asm volatile("mma.sync.aligned.m16n8k16.row.col.f32.bf16.bf16.f32 "
        "{%0,%1,%2,%3},{%4,%5,%6,%7},{%8,%9},{%0,%1,%2,%3};"
        :"+f"(c[0]),"+f"(c[1]),"+f"(c[2]),"+f"(c[3])
        :"r"(a[0]),"r"(a[1]),"r"(a[2]),"r"(a[3]),"r"(b[0]),"r"(b[1]));
}

#define STG 20480
#define GSMEM (4*STG)

#define MMA_COMPUTE(ta, tb) \
    _Pragma("unroll") \
    for (int s = 0; s < 2; s++) { \
        uint32_t af[4][4], bq[4][2]; \
        _Pragma("unroll") \
        for (int mt = 0; mt < 4; mt++) \
            ldmx4(af[mt], (ta) + (uint32_t)((wm*64+mt*16+(g&1)*8+r8)*80 + (g>>1)*16 + s*32)); \
        _Pragma("unroll") \
        for (int np = 0; np < 2; np++) { \
            uint32_t t4[4]; \
            ldmx4(t4, (tb) + (uint32_t)((wn*32+np*16+(g>>1)*8+r8)*80 + (g&1)*16 + s*32)); \
            bq[np*2][0]=t4[0]; bq[np*2][1]=t4[1]; bq[np*2+1][0]=t4[2]; bq[np*2+1][1]=t4[3]; \
        } \
        _Pragma("unroll") \
        for (int mt = 0; mt < 4; mt++) \
            _Pragma("unroll") \
            for (int nt = 0; nt < 4; nt++) \
                mma_bf16(acc[mt][nt], af[mt], bq[nt]); \
    }

#define GEMM_MAINLOOP(Aptr, Bptr, MMd, NNd, KKd, llda, lldb) \
    const int rowL = tid>>1, sgA = (tid&1)*2; \
    const bool vA = (m0+rowL)<(MMd), vB = (n0+rowL)<(NNd); \
    const bf16* pA = (Aptr) + (vA?((size_t)(m0+rowL)*(llda)):0) + sgA*8; \
    const bf16* pB = (Bptr) + (vB?((size_t)(n0+rowL)*(lldb)):0) + sgA*8; \
    const uint32_t dA = rowL*80+sgA*16, dB = 10240+rowL*80+sgA*16; \
    auto LD = [&](int c){ \
        if (c < NC) { \
            uint32_t st = sb + (c&3)*STG; \
            int k0 = c<<5; \
            bool k0ok = (k0+sgA*8)<(KKd), k1ok = (k0+sgA*8+8)<(KKd); \
            cpa16(st+dA,    pA+k0,   vA&&k0ok); \
            cpa16(st+dA+16, pA+k0+8, vA&&k1ok); \
            cpa16(st+dB,    pB+k0,   vB&&k0ok); \
            cpa16(st+dB+16, pB+k0+8, vB&&k1ok); \
        } \
        asm volatile("cp.async.commit_group;":::"memory"); \
    }; \
    LD(0); LD(1); LD(2); \
    for (int c=0;c<NC;c++){ \
        asm volatile("cp.async.wait_group 2;":::"memory"); \
        __syncthreads(); \
        uint32_t ta = sb+(c&3)*STG, tb = ta+10240; \
        MMA_COMPUTE(ta, tb); \
        LD(c+3); \
    }

template<int OUTM>
__device__ __forceinline__ void gbody(const bf16* __restrict__ A, const bf16* __restrict__ B,
    void* __restrict__ Cv, int Md, int Nd, int Kd, int lda, int ldb, int ldc, int m0, int n0)
{
    extern __shared__ char smc[];
    const int tid = threadIdx.x, lane = tid&31, wid = tid>>5;
    const int wm = wid>>2, wn = wid&3, g = lane>>3, r8 = lane&7;
    uint32_t sb = smem_u32(smc);
    float acc[4][4][4];
#pragma unroll
    for (int a=0;a<4;a++)
#pragma unroll
        for (int b=0;b<4;b++)
#pragma unroll
            for (int c=0;c<4;c++) acc[a][b][c]=0.f;
    const int NC = (Kd+31)>>5;
    GEMM_MAINLOOP(A, B, Md, Nd, Kd, lda, ldb)
#pragma unroll
    for (int mt=0;mt<4;mt++){
        int r0 = m0+wm*64+mt*16+(lane>>2);
#pragma unroll
        for (int nt=0;nt<4;nt++){
            int c0 = n0+wn*32+nt*8+(lane&3)*2;
            if (c0 >= Nd) continue;
            float x0=acc[mt][nt][0],x1=acc[mt][nt][1],x2=acc[mt][nt][2],x3=acc[mt][nt][3];
            if (OUTM==0){
                float* C=(float*)Cv;
                if (r0<Md)   *(float2*)&C[(size_t)r0*ldc+c0]     = make_float2(x0,x1);
                if (r0+8<Md) *(float2*)&C[(size_t)(r0+8)*ldc+c0] = make_float2(x2,x3);
            } else {
                bf16* C=(bf16*)Cv;
                if (r0<Md)   *(bf162*)&C[(size_t)r0*ldc+c0]     = __floats2bfloat162_rn(x0,x1);
                if (r0+8<Md) *(bf162*)&C[(size_t)(r0+8)*ldc+c0] = __floats2bfloat162_rn(x2,x3);
            }
        }
    }
}

template<int OUTM>
__global__ void __launch_bounds__(256,2)
bgemm(const bf16* __restrict__ A, const bf16* __restrict__ B, void* __restrict__ Cv,
      int Md, int Nd, int Kd, int lda, int ldb, int ldc, size_t sA, size_t sB, size_t sC)
{
    const int z = blockIdx.z;
    void* C = (OUTM==0) ? (void*)((float*)Cv+(size_t)z*sC) : (void*)((bf16*)Cv+(size_t)z*sC);
    gbody<OUTM>(A+(size_t)z*sA, B+(size_t)z*sB, C, Md, Nd, Kd, lda, ldb, ldc,
                blockIdx.y*128, blockIdx.x*128);
}

// S GEMM: E=exp(WvT·VbT^T) and ET (transposed via swizzled smem staging)
__global__ void __launch_bounds__(256,2)
sgemm(const bf16* __restrict__ WvT, const bf16* __restrict__ VbT,
      bf16* __restrict__ Ep, bf16* __restrict__ ETp)
{
    extern __shared__ char smc[];
    const int z = blockIdx.z;
    const bf16* A = WvT + (size_t)z*NCn;
    const bf16* B = VbT + (size_t)z*NCn;
    bf16* Eb  = Ep  + (size_t)z*NN;
    bf16* ETb = ETp + (size_t)z*NN;
    const int m0 = blockIdx.y*128, n0 = blockIdx.x*128;
    const int tid = threadIdx.x, lane = tid&31, wid = tid>>5;
    const int wm = wid>>2, wn = wid&3, g = lane>>3, r8 = lane&7;
    uint32_t sb = smem_u32(smc);
    float acc[4][4][4];
#pragma unroll
    for (int a=0;a<4;a++)
#pragma unroll
        for (int b=0;b<4;b++)
#pragma unroll
            for (int c=0;c<4;c++) acc[a][b][c]=0.f;
    const int NC = 8;
    GEMM_MAINLOOP(A, B, NPix, NPix, CC, CC, CC)

    __syncthreads();
    bf16* sh = (bf16*)smc;
#pragma unroll
    for (int mt=0;mt<4;mt++){
        int rl0 = wm*64+mt*16+(lane>>2);
        int r0 = m0+rl0;
        bool rok0 = r0<NPix, rok1 = (r0+8)<NPix;
#pragma unroll
        for (int nt=0;nt<4;nt++){
            int cl0 = wn*32+nt*8+(lane&3)*2;
            int c0 = n0+cl0;
            bool cok = c0<NPix;
            float x0=__expf(acc[mt][nt][0]),x1=__expf(acc[mt][nt][1]);
            float x2=__expf(acc[mt][nt][2]),x3=__expf(acc[mt][nt][3]);
            if (cok) {
                if (rok0) *(bf162*)&Eb[(size_t)r0*NPix+c0]     = __floats2bfloat162_rn(x0,x1);
                if (rok1) *(bf162*)&Eb[(size_t)(r0+8)*NPix+c0] = __floats2bfloat162_rn(x2,x3);
            }
#define TST(rr,cc,xx) sh[(cc)*136 + (((((rr)>>3)^((cc)>>3))&15)<<3) + ((rr)&7)] = __float2bfloat16(xx)
            TST(rl0,   cl0,   x0); TST(rl0,   cl0+1, x1);
            TST(rl0+8, cl0,   x2); TST(rl0+8, cl0+1, x3);
#undef TST
        }
    }
    __syncthreads();
#pragma unroll
    for (int rr=0; rr<16; rr++){
        int cp2 = wid*16 + rr;
        int mg = n0 + cp2;
        if (mg >= NPix) continue;
        int cb = cp2>>3;
        int rb = lane>>1, half = lane&1;
        int ng = m0 + rb*8 + half*4;
        if (ng >= NPix) continue;
        uint2 v = *(uint2*)(sh + cp2*136 + (((rb^cb)&15)<<3) + half*4);
        *(uint2*)&ETb[(size_t)mg*NPix + ng] = v;
    }
}

// ===== fused Z GEMM (64x256) + in-kernel rowsum + normalize + gate + bf16 store =====
#define ZSTG 25600
#define ZSMEM (4*ZSTG)
__global__ void __launch_bounds__(256,2)
zfused(const bf16* __restrict__ E, const bf16* __restrict__ ET,
       const bf16* __restrict__ Vab, const bf16* __restrict__ Vbb,
       const float* __restrict__ gw,
       bf16* __restrict__ a1b, bf16* __restrict__ a2b)
{
    extern __shared__ char smc[];
    int z = blockIdx.z, br = z>>1, b = z&1;
    const bf16* A = (br?ET:E) + (size_t)b*NN;
    const bf16* B = (br?Vab:Vbb) + (size_t)b*CN;
    bf16* out = (br?a2b:a1b) + (size_t)b*NCn;
    const int m0 = blockIdx.y*64;
    const int tid = threadIdx.x, lane = tid&31, wid = tid>>5;
    const int wm = wid>>2, wn = wid&3, g = lane>>3, r8 = lane&7;
    uint32_t sb = smem_u32(smc);
    float acc[2][8][4];
#pragma unroll
    for (int a=0;a<2;a++)
#pragma unroll
        for (int bb=0;bb<8;bb++)
#pragma unroll
            for (int c=0;c<4;c++) acc[a][bb][c]=0.f;
    const int NC = 113;

    const int rowA = tid>>2, sgA = tid&3;
    const bool vA = (m0+rowA)<NPix;
    const bf16* pA = A + (vA?((size_t)(m0+rowA)*NPix):0) + sgA*8;
    const bf16* pB = B + (size_t)rowA*NPix + sgA*8;
    const uint32_t dA = rowA*80 + sgA*16;
    const uint32_t dB = 5120 + rowA*80 + sgA*16;
    auto LD = [&](int c){
        if (c < NC) {
            uint32_t st = sb + (c&3)*ZSTG;
            int k0 = c<<5;
            bool kok = (k0+sgA*8) < NPix;
            cpa16(st+dA, pA+k0, vA&&kok);
#pragma unroll
            for (int q=0;q<4;q++)
                cpa16(st+dB + q*64*80, pB + (size_t)q*64*NPix + k0, kok);
        }
        asm volatile("cp.async.commit_group;":::"memory");
    };
    LD(0); LD(1); LD(2);
    float rs = 0.f;
    for (int c=0;c<NC;c++){
        asm volatile("cp.async.wait_group 2;":::"memory");
        __syncthreads();
        uint32_t ta = sb+(c&3)*ZSTG, tb = ta+5120;
        {
            const uint4 v4 = *(const uint4*)(smc + (size_t)(c&3)*ZSTG + rowA*80 + sgA*16);
            const uint32_t vv[4] = {v4.x, v4.y, v4.z, v4.w};
#pragma unroll
            for (int u=0;u<4;u++){
                float2 f = __bfloat1622float2(*(const bf162*)&vv[u]);
                rs += f.x + f.y;
            }
        }
#pragma unroll
        for (int s=0;s<2;s++){
            uint32_t af[2][4], bq[8][2];
#pragma unroll
            for (int mt=0;mt<2;mt++)
                ldmx4(af[mt], ta + (uint32_t)((wm*32+mt*16+(g&1)*8+r8)*80 + (g>>1)*16 + s*32));
#pragma unroll
            for (int np=0;np<4;np++){
                uint32_t t4[4];
                ldmx4(t4, tb + (uint32_t)((wn*64+np*16+(g>>1)*8+r8)*80 + (g&1)*16 + s*32));
                bq[np*2][0]=t4[0]; bq[np*2][1]=t4[1]; bq[np*2+1][0]=t4[2]; bq[np*2+1][1]=t4[3];
            }
#pragma unroll
            for (int mt=0;mt<2;mt++)
#pragma unroll
                for (int nt=0;nt<8;nt++)
                    mma_bf16(acc[mt][nt], af[mt], bq[nt]);
        }
        LD(c+3);
    }
    rs += __shfl_xor_sync(~0u, rs, 1);
    rs += __shfl_xor_sync(~0u, rs, 2);

    float gwv[8][2];
#pragma unroll
    for (int nt=0;nt<8;nt++){
        int c0 = wn*64+nt*8+(lane&3)*2;
        gwv[nt][0]=gw[c0]; gwv[nt][1]=gw[c0+1];
    }
    float praw[2][2]={{0,0},{0,0}};
#pragma unroll
    for (int mt=0;mt<2;mt++)
#pragma unroll
        for (int nt=0;nt<8;nt++){
            praw[mt][0] += gwv[nt][0]*acc[mt][nt][0] + gwv[nt][1]*acc[mt][nt][1];
            praw[mt][1] += gwv[nt][0]*acc[mt][nt][2] + gwv[nt][1]*acc[mt][nt][3];
        }
#pragma unroll
    for (int mt=0;mt<2;mt++)
#pragma unroll
        for (int o=1;o<=2;o<<=1){
            praw[mt][0]+=__shfl_xor_sync(~0u,praw[mt][0],o);
            praw[mt][1]+=__shfl_xor_sync(~0u,praw[mt][1],o);
        }
    __syncthreads();
    float* dotv  = (float*)smc;
    float* rsums = (float*)smc + 256;
    if ((lane&3)==0){
#pragma unroll
        for (int mt=0;mt<2;mt++){
            int rl = wm*32+mt*16+(lane>>2);
            dotv[wn*64 + rl]     = praw[mt][0];
            dotv[wn*64 + rl + 8] = praw[mt][1];
        }
    }
    if (sgA==0) rsums[rowA] = rs;
    __syncthreads();
#pragma unroll
    for (int mt=0;mt<2;mt++){
#pragma unroll
        for (int hf=0;hf<2;hf++){
            int rl = wm*32+mt*16+hf*8+(lane>>2);
            int r = m0+rl;
            if (r >= NPix) continue;
            float d = dotv[rl] + dotv[64+rl] + dotv[128+rl] + dotv[192+rl];
            float v = 1.f/rsums[rl];
            float mul = v/(1.f+__expf(-d*v));
#pragma unroll
            for (int nt=0;nt<8;nt++){
                int c0 = wn*64+nt*8+(lane&3)*2;
                *(bf162*)&out[(size_t)r*CC+c0] =
                    __floats2bfloat162_rn(acc[mt][nt][hf*2]*mul, acc[mt][nt][hf*2+1]*mul);
            }
        }
    }
}

// convs + fused BN partials: z=0,1 conv1 (3 srcs), z=2,3 conv2 (2 srcs)
__global__ void __launch_bounds__(256,2)
convpair(const bf16* __restrict__ a1b, const bf16* __restrict__ a2b,
         const bf16* __restrict__ VaT, const bf16* __restrict__ VbT, const bf16* __restrict__ DaT,
         const bf16* __restrict__ wr1, const bf16* __restrict__ wr2,
         float* __restrict__ x1T, float* __restrict__ x2T,
         float* __restrict__ ps, float* __restrict__ pq)
{
    extern __shared__ char smc[];
    int zz = blockIdx.z, br = zz>>1, b = zz&1;
    const bf16 *s0 = br?a2b:a1b, *s1 = br?VbT:VaT, *s2 = br?VbT:DaT;
    const bf16 *W = br?wr2:wr1;
    float* out = br?x2T:x1T;
    const int SR = br?2:3;
    const int LDB = SR*256, KPC = SR*8, NC = 9*KPC;
    const size_t so = (size_t)b*NCn;
    const int m0 = blockIdx.y*128, n0 = blockIdx.x*128;
    const int tid = threadIdx.x, lane = tid&31, wid = tid>>5;
    const int wm = wid>>2, wn = wid&3, g = lane>>3, r8 = lane&7;
    uint32_t sb = smem_u32(smc);
    float acc[4][4][4];
#pragma unroll
    for (int a=0;a<4;a++)
#pragma unroll
        for (int bb=0;bb<4;bb++)
#pragma unroll
            for (int c=0;c<4;c++) acc[a][bb][c]=0.f;

    const int rowL = tid>>1, sgA = (tid&1)*2;
    const int j = m0+rowL;
    const bool jv = j<NPix;
    const int h = (jv?j:0)/60, w = (jv?j:0) - ((jv?j:0)/60)*60;
    uint32_t vmask = 0;
#pragma unroll
    for (int rr=0;rr<9;rr++){
        int dh = rr/3-1, dw = rr-(rr/3)*3-1;
        if (jv && (unsigned)(h+dh)<60u && (unsigned)(w+dw)<60u) vmask |= 1u<<rr;
    }
    const size_t jb = (size_t)(jv?j:0)*CC + sgA*8;
    const bf16 *pS0 = s0+so+jb, *pS1 = s1+so+jb, *pS2 = s2+so+jb;
    const bf16 *pW = W + (size_t)(n0+rowL)*LDB + sgA*8;
    const uint32_t dAs = rowL*80+sgA*16, dBs = 10240+rowL*80+sgA*16;

    int ld_vc = 0, ld_rr = 0, ld_kc = 0, ld_dh = -1, ld_dw = -1;
    size_t woff = 0;
    auto LD = [&](){
        if (ld_vc < NC) {
            uint32_t st = sb + (ld_vc&3)*STG;
            bool vv = (vmask>>ld_rr)&1;
            int off = ld_dh*60 + ld_dw;
            int srcSel = ld_kc>>3;
            const bf16* sp = (srcSel==0)?pS0:((srcSel==1)?pS1:pS2);
            const bf16* ap = sp + (intptr_t)off*CC + (ld_kc&7)*32;
            cpa16(st+dAs,    vv?ap:s0,     vv);
            cpa16(st+dAs+16, vv?(ap+8):s0, vv);
            cpa16(st+dBs,    pW+woff,   true);
            cpa16(st+dBs+16, pW+woff+8, true);
            ld_vc++; ld_kc++; woff += 32;
            if (ld_kc == KPC) {
                ld_kc = 0; ld_rr++;
                woff += (size_t)(CC-1)*LDB;
                ld_dw++; if (ld_dw==2){ ld_dw=-1; ld_dh++; }
            }
        }
        asm volatile("cp.async.commit_group;":::"memory");
    };
    LD(); LD(); LD();
    for (int c=0;c<NC;c++){
        asm volatile("cp.async.wait_group 2;":::"memory");
        __syncthreads();
        uint32_t ta = sb+(c&3)*STG, tb = ta+10240;
        MMA_COMPUTE(ta, tb);
        LD();
    }
    float* C = out + so;
    float bs[4][2], bqv[4][2];
#pragma unroll
    for (int nt=0;nt<4;nt++){ bs[nt][0]=bs[nt][1]=0.f; bqv[nt][0]=bqv[nt][1]=0.f; }
#pragma unroll
    for (int mt=0;mt<4;mt++){
        int r0 = m0+wm*64+mt*16+(lane>>2);
        bool rok0 = r0<NPix, rok1 = (r0+8)<NPix;
#pragma unroll
        for (int nt=0;nt<4;nt++){
            int c0 = n0+wn*32+nt*8+(lane&3)*2;
            float x0=acc[mt][nt][0],x1=acc[mt][nt][1],x2=acc[mt][nt][2],x3=acc[mt][nt][3];
            if (rok0){
                *(float2*)&C[(size_t)r0*CC+c0] = make_float2(x0,x1);
                bs[nt][0]+=x0; bs[nt][1]+=x1; bqv[nt][0]+=x0*x0; bqv[nt][1]+=x1*x1;
            }
            if (rok1){
                *(float2*)&C[(size_t)(r0+8)*CC+c0] = make_float2(x2,x3);
                bs[nt][0]+=x2; bs[nt][1]+=x3; bqv[nt][0]+=x2*x2; bqv[nt][1]+=x3*x3;
            }
        }
    }
    // reduce across the 8 row-lanes (stride-4 groups)
#pragma unroll
    for (int nt=0;nt<4;nt++)
#pragma unroll
        for (int e=0;e<2;e++)
#pragma unroll
            for (int o=4;o<=16;o<<=1){
                bs[nt][e]  += __shfl_xor_sync(~0u, bs[nt][e],  o);
                bqv[nt][e] += __shfl_xor_sync(~0u, bqv[nt][e], o);
            }
    __syncthreads();      // stage smem free
    float* sarr = (float*)smc;          // [wm 2][128]
    float* qarr = (float*)smc + 256;    // [wm 2][128]
    if (lane < 4){
#pragma unroll
        for (int nt=0;nt<4;nt++){
            int cl = wn*32+nt*8+(lane&3)*2;
            sarr[wm*128+cl]   = bs[nt][0];  sarr[wm*128+cl+1] = bs[nt][1];
            qarr[wm*128+cl]   = bqv[nt][0]; qarr[wm*128+cl+1] = bqv[nt][1];
        }
    }
    __syncthreads();
    if (tid < 128){
        int p = br*58 + b*29 + blockIdx.y;
        ps[p*CC + n0 + tid] = sarr[tid] + sarr[128+tid];
        pq[p*CC + n0 + tid] = qarr[tid] + qarr[128+tid];
    }
}

__global__ void wprep(const float* __restrict__ W_e, const float* __restrict__ c1w,
                      const float* __restrict__ c2w, bf16* __restrict__ Web,
                      bf16* __restrict__ wr1, bf16* __restrict__ wr2)
{
    int idx = blockIdx.x*256+threadIdx.x;
    const int N0 = CC*CC, N1 = 9*CC*768, N2 = 9*CC*512;
    if (idx < N0) { Web[idx] = __float2bfloat16(W_e[idx]); return; }
    idx -= N0;
    if (idx < N1) {
        int r = idx/(CC*768), rem = idx - r*(CC*768);
        int co = rem/768, ci = rem - co*768;
        wr1[idx] = __float2bfloat16(c1w[(size_t)co*768*9 + ci*9 + r]);
        return;
    }
    idx -= N1;
    if (idx < N2) {
        int r = idx/(CC*512), rem = idx - r*(CC*512);
        int co = rem/512, ci = rem - co*512;
        wr2[idx] = __float2bfloat16(c2w[(size_t)co*512*9 + ci*9 + r]);
    }
}

__global__ void trans3(const float* __restrict__ Va, const float* __restrict__ Vb,
                       const float* __restrict__ Da,
                       bf16* __restrict__ VaT, bf16* __restrict__ VbT, bf16* __restrict__ DaT,
                       bf16* __restrict__ Vab, bf16* __restrict__ Vbb)
{
    __shared__ float t[32][33];
    int z = blockIdx.z, src = z>>1, b = z&1;
    const float* in = (src==0?Va:(src==1?Vb:Da)) + (size_t)b*CN;
    bf16* outT = (src==0?VaT:(src==1?VbT:DaT)) + (size_t)b*NCn;
    bf16* outN = (src==0?Vab:(src==1?Vbb:(bf16*)nullptr));
    if (outN) outN += (size_t)b*CN;
    int c0 = blockIdx.x*32, r0 = blockIdx.y*32;
    int tx = threadIdx.x&31, ty = threadIdx.x>>5;
#pragma unroll
    for (int i=0;i<4;i++){
        int rr=r0+ty+i*8, cc=c0+tx;
        if (cc<NPix){
            float v = in[(size_t)rr*NPix+cc];
            t[ty+i*8][tx] = v;
            if (outN) outN[(size_t)rr*NPix+cc] = __float2bfloat16(v);
        }
    }
    __syncthreads();
#pragma unroll
    for (int i=0;i<4;i++){
        int cc=c0+ty+i*8, rr=r0+tx;
        if (cc<NPix) outT[(size_t)cc*CC+rr] = __float2bfloat16(t[tx][ty+i*8]);
    }
}

__global__ void bncomb_k(const float* __restrict__ ps, const float* __restrict__ pq,
                         const float* __restrict__ g1, const float* __restrict__ b1,
                         const float* __restrict__ g2, const float* __restrict__ b2,
                         float* __restrict__ sc, float* __restrict__ sh)
{
    int c = threadIdx.x, z = blockIdx.x;
    float s=0.f, q=0.f;
    for (int p=z*58;p<z*58+58;p++){ s+=ps[p*CC+c]; q+=pq[p*CC+c]; }
    const float inv = 1.f/(BB*NPix);
    float mean=s*inv, var=q*inv-mean*mean;
    float k = (z?g2:g1)[c]*rsqrtf(var+1e-5f);
    sc[z*CC+c]=k; sh[z*CC+c]=(z?b2:b1)[c]-mean*k;
}

__global__ void bncls_k(const float* __restrict__ x1T, const float* __restrict__ x2T,
                        const float* __restrict__ sc, const float* __restrict__ sh,
                        const float* __restrict__ c1w, const float* __restrict__ c1b,
                        const float* __restrict__ c2w, const float* __restrict__ c2b,
                        float* __restrict__ y1, float* __restrict__ y2)
{
    int z = blockIdx.z;
    const float* x = z?x2T:x1T;
    const float* cw = z?c2w:c1w;
    const float* cb = z?c2b:c1b;
    float* y = z?y2:y1;
    __shared__ float ssc[CC], ssh[CC], w0[CC], w1[CC];
    int tid = threadIdx.x;
    for (int c=tid;c<CC;c+=256){ ssc[c]=sc[z*CC+c]; ssh[c]=sh[z*CC+c]; w0[c]=cw[c]; w1[c]=cw[CC+c]; }
    __syncthreads();
    int lane=tid&31, wid=tid>>5;
    int p = blockIdx.x*8+wid, b = blockIdx.y;
    const float* xp = x + ((size_t)b*NPix+p)*CC + lane*8;
    float4 u0=*(const float4*)xp, u1=*(const float4*)(xp+4);
    float vv[8]={u0.x,u0.y,u0.z,u0.w,u1.x,u1.y,u1.z,u1.w};
    int c8=lane*8;
    float a0=0.f, a1=0.f;
#pragma unroll
    for (int u=0;u<8;u++){
        float v = fmaxf(vv[u]*ssc[c8+u]+ssh[c8+u], 0.f);
        a0 += v*w0[c8+u]; a1 += v*w1[c8+u];
    }
#pragma unroll
    for (int o=16;o;o>>=1){ a0+=__shfl_xor_sync(~0u,a0,o); a1+=__shfl_xor_sync(~0u,a1,o); }
    if (lane==0){
        y[(size_t)(b*NCls+0)*NPix+p] = a0+cb[0];
        y[(size_t)(b*NCls+1)*NPix+p] = a1+cb[1];
    }
}

__global__ void resize_k(float* __restrict__ out)
{
    const size_t per = (size_t)BB*NCls*HOUT*WOUT;
    size_t idx = (size_t)blockIdx.x*256+threadIdx.x;
    if (idx >= 2*per) return;
    int t = idx >= per;
    size_t r = idx - (size_t)t*per;
    int x=(int)(r%WOUT); r/=WOUT;
    int y=(int)(r%HOUT); r/=HOUT;
    int kc=(int)(r%NCls); int b=(int)(r/NCls);
    const float* src = (t?g_y2:g_y1) + (size_t)(b*NCls+kc)*NPix;
    const float sc = 60.f/473.f;
    float syf=(y+0.5f)*sc-0.5f, sxf=(x+0.5f)*sc-0.5f;
    float fy0=floorf(syf), fx0=floorf(sxf);
    float fy=syf-fy0, fx=sxf-fx0;
    int y0=max((int)fy0,0), x0=max((int)fx0,0);
    int y1i=min((int)fy0+1,59), x1i=min((int)fx0+1,59);
    float v00=src[y0*60+x0], v01=src[y0*60+x1i], v10=src[y1i*60+x0], v11=src[y1i*60+x1i];
    float vt=v00+(v01-v00)*fx, vb=v10+(v11-v10)*fx;
    out[idx] = 1.f/(1.f+__expf(-(vt+(vb-vt)*fy)));
}

extern "C" void kernel_launch(void* const* d_in, const int* in_sizes, int n_in,
                              void* d_out, int out_size)
{
    const float *V_a=(const float*)d_in[0], *V_b=(const float*)d_in[1], *D_a=(const float*)d_in[2];
    const float *W_e=(const float*)d_in[3], *gate_w=(const float*)d_in[4];
    const float *c1w=(const float*)d_in[5], *c2w=(const float*)d_in[6];
    const float *bn1g=(const float*)d_in[7], *bn1b=(const float*)d_in[8];
    const float *bn2g=(const float*)d_in[9], *bn2b=(const float*)d_in[10];
    const float *cl1w=(const float*)d_in[11], *cl1b=(const float*)d_in[12];
    const float *cl2w=(const float*)d_in[13], *cl2b=(const float*)d_in[14];
    float* out = (float*)d_out;

    bf16 *Vab,*Vbb,*Web,*wr1,*wr2,*VaT,*VbT,*DaT,*WvT,*E,*ET,*a1b,*a2b;
    float *x1T,*x2T,*bp,*bq,*bsc,*bsh,*y1,*y2;
    cudaGetSymbolAddress((void**)&Vab,g_Vab);  cudaGetSymbolAddress((void**)&Vbb,g_Vbb);
    cudaGetSymbolAddress((void**)&Web,g_Web);  cudaGetSymbolAddress((void**)&wr1,g_wr1);
    cudaGetSymbolAddress((void**)&wr2,g_wr2);  cudaGetSymbolAddress((void**)&VaT,g_VaT);
    cudaGetSymbolAddress((void**)&VbT,g_VbT);  cudaGetSymbolAddress((void**)&DaT,g_DaT);
    cudaGetSymbolAddress((void**)&WvT,g_WvT);  cudaGetSymbolAddress((void**)&E,g_E);
    cudaGetSymbolAddress((void**)&ET,g_ET);
    cudaGetSymbolAddress((void**)&a1b,g_a1Tb); cudaGetSymbolAddress((void**)&a2b,g_a2Tb);
    cudaGetSymbolAddress((void**)&x1T,g_x1T);  cudaGetSymbolAddress((void**)&x2T,g_x2T);
    cudaGetSymbolAddress((void**)&bp,g_bp);    cudaGetSymbolAddress((void**)&bq,g_bq);
    cudaGetSymbolAddress((void**)&bsc,g_bnsc); cudaGetSymbolAddress((void**)&bsh,g_bnsh);
    cudaGetSymbolAddress((void**)&y1,g_y1);    cudaGetSymbolAddress((void**)&y2,g_y2);

    cudaFuncSetAttribute(bgemm<1>, cudaFuncAttributeMaxDynamicSharedMemorySize, GSMEM);
    cudaFuncSetAttribute(sgemm,    cudaFuncAttributeMaxDynamicSharedMemorySize, GSMEM);
    cudaFuncSetAttribute(zfused,   cudaFuncAttributeMaxDynamicSharedMemorySize, ZSMEM);
    cudaFuncSetAttribute(convpair, cudaFuncAttributeMaxDynamicSharedMemorySize, GSMEM);

    const int WTOT = CC*CC + 9*CC*768 + 9*CC*512;
    wprep<<<(WTOT+255)/256,256>>>(W_e, c1w, c2w, Web, wr1, wr2);
    trans3<<<dim3(113,8,6),256>>>(V_a, V_b, D_a, VaT, VbT, DaT, Vab, Vbb);
    bgemm<1><<<dim3(2,29,BB),256,GSMEM>>>(VaT, Web, WvT, NPix, CC, CC, CC, CC, CC, NCn, 0, NCn);
    sgemm<<<dim3(29,29,BB),256,GSMEM>>>(WvT, VbT, E, ET);
    zfused<<<dim3(1,57,4),256,ZSMEM>>>(E, ET, Vab, Vbb, gate_w, a1b, a2b);
    convpair<<<dim3(2,29,4),256,GSMEM>>>(a1b, a2b, VaT, VbT, DaT, wr1, wr2, x1T, x2T, bp, bq);
    bncomb_k<<<2,256>>>(bp, bq, bn1g, bn1b, bn2g, bn2b, bsc, bsh);
    bncls_k<<<dim3(450,BB,2),256>>>(x1T, x2T, bsc, bsh, cl1w, cl1b, cl2w, cl2b, y1, y2);
    const size_t total = 2ull*BB*NCls*HOUT*WOUT;
    resize_k<<<(int)((total+255)/256),256>>>(out);
}